// round 3
// baseline (speedup 1.0000x reference)
#include <cuda_runtime.h>

// Problem constants
#define BB    32
#define CIN   64
#define HIN   128
#define WIN   128
#define COUT  128
#define OH    126
#define OW    126
#define NG    16
#define CPG   8
#define PH    63
#define PW    63
#define GN_EPS 1e-5f

typedef unsigned long long u64;

__device__ float g_y[(size_t)BB * COUT * OH * OW];
__device__ float g_mean[BB * NG];
__device__ float g_rstd[BB * NG];

__device__ __forceinline__ u64 ffma2(u64 a, u64 b, u64 c) {
    u64 d;
    asm("fma.rn.f32x2 %0, %1, %2, %3;" : "=l"(d) : "l"(a), "l"(b), "l"(c));
    return d;
}
__device__ __forceinline__ void unpack2(u64 v, float& lo, float& hi) {
    asm("mov.b64 {%0, %1}, %2;" : "=f"(lo), "=f"(hi) : "l"(v));
}

// ---------------------------------------------------------------------------
// Kernel 1: direct 3x3 conv (VALID) + bias -> g_y
// Block: 16 output channels x 16x16 pixel tile.
// Thread: 2 channels (packed f32x2) x 4x2 pixels.  256 thr = 8 chpair x 32 pos.
// x tile stored DUPLICATED in smem -> broadcast pairs via LDS.128, no MOVs.
// Weights stored channel-paired -> LDS.64, no MOVs.
// ---------------------------------------------------------------------------
#define CO_T 16
#define CI_T 8
#define TILE 16
#define XROW 40   // duplicated row: 20 dup values = 40 floats = 160B

__global__ __launch_bounds__(256, 3)
void conv_kernel(const float* __restrict__ x,
                 const float* __restrict__ w,
                 const float* __restrict__ bias)
{
    __shared__ __align__(16) float  xs2[CI_T][18][XROW];      // duplicated values
    __shared__ __align__(16) float2 ws2[CO_T / 2][CI_T][9];   // channel pairs

    const int bx  = blockIdx.x;            // 8 tiles in x
    const int by  = blockIdx.y;            // 8 tiles in y
    const int bz  = blockIdx.z;            // b * 8 + co_tile
    const int b   = bz >> 3;
    const int co0 = (bz & 7) * CO_T;
    const int oy0 = by * TILE;
    const int ox0 = bx * TILE;

    const int tid  = threadIdx.x;
    const int cp   = tid >> 5;             // channel pair 0..7
    const int pos  = tid & 31;
    const int px0  = (pos & 3) * 4;        // 0,4,8,12
    const int py0  = (pos >> 2) * 2;       // 0,2,...,14

    u64 acc2[2][4];
#pragma unroll
    for (int i = 0; i < 2; i++)
#pragma unroll
        for (int j = 0; j < 4; j++) acc2[i][j] = 0ull;

    for (int ci0 = 0; ci0 < CIN; ci0 += CI_T) {
        // ---- x tile: 8cc x 18rows x 5 float4 (cols 0..19), duplicated store ----
#pragma unroll
        for (int it = 0; it < 3; it++) {
            int idx = tid + it * 256;
            if (idx < CI_T * 18 * 5) {
                int cc  = idx / 90;
                int rem = idx - cc * 90;
                int r   = rem / 5;
                int q   = rem - r * 5;
                int gy  = oy0 + r;
                int gx  = ox0 + 4 * q;
                float4 v = make_float4(0.f, 0.f, 0.f, 0.f);
                if (gy < HIN && gx < WIN)
                    v = *reinterpret_cast<const float4*>(
                        &x[(((size_t)b * CIN + ci0 + cc) * HIN + gy) * WIN + gx]);
                float* dst = &xs2[cc][r][8 * q];
                *reinterpret_cast<float4*>(dst)     = make_float4(v.x, v.x, v.y, v.y);
                *reinterpret_cast<float4*>(dst + 4) = make_float4(v.z, v.z, v.w, v.w);
            }
        }
        // ---- weights: 8 pairs x 8cc x 9 taps ----
#pragma unroll
        for (int it = 0; it < 3; it++) {
            int idx = tid + it * 256;
            if (idx < (CO_T / 2) * CI_T * 9) {
                int p   = idx / 72;
                int rem = idx - p * 72;
                int cc  = rem / 9;
                int k   = rem - cc * 9;
                int co  = co0 + 2 * p;
                float w0 = w[((size_t)co       * CIN + ci0 + cc) * 9 + k];
                float w1 = w[((size_t)(co + 1) * CIN + ci0 + cc) * 9 + k];
                ws2[p][cc][k] = make_float2(w0, w1);
            }
        }
        __syncthreads();

#pragma unroll
        for (int cc = 0; cc < CI_T; cc++) {
            u64 wp[9];
#pragma unroll
            for (int k = 0; k < 9; k++)
                wp[k] = *reinterpret_cast<const u64*>(&ws2[cp][cc][k]);   // LDS.64 bcast

#pragma unroll
            for (int rl = 0; rl < 4; rl++) {
                // 6 broadcast pairs P[i] = (x[px0+i], x[px0+i]) via 3 LDS.128
                u64 P[6];
                const float* rowp = &xs2[cc][py0 + rl][2 * px0];
#pragma unroll
                for (int t = 0; t < 3; t++) {
                    ulonglong2 q = *reinterpret_cast<const ulonglong2*>(rowp + 4 * t);
                    P[2 * t]     = q.x;
                    P[2 * t + 1] = q.y;
                }
#pragma unroll
                for (int iy = 0; iy < 2; iy++) {
                    const int kr = rl - iy;
                    if (kr < 0 || kr > 2) continue;
#pragma unroll
                    for (int kc = 0; kc < 3; kc++) {
                        const u64 wv = wp[kr * 3 + kc];
                        acc2[iy][0] = ffma2(P[0 + kc], wv, acc2[iy][0]);
                        acc2[iy][1] = ffma2(P[1 + kc], wv, acc2[iy][1]);
                        acc2[iy][2] = ffma2(P[2 + kc], wv, acc2[iy][2]);
                        acc2[iy][3] = ffma2(P[3 + kc], wv, acc2[iy][3]);
                    }
                }
            }
        }
        __syncthreads();
    }

    const int   co  = co0 + 2 * cp;
    const float bv0 = bias[co];
    const float bv1 = bias[co + 1];
#pragma unroll
    for (int iy = 0; iy < 2; iy++) {
        const int oy = oy0 + py0 + iy;
        if (oy >= OH) continue;
        float* yp0 = &g_y[(((size_t)b * COUT + co)     * OH + oy) * OW];
        float* yp1 = &g_y[(((size_t)b * COUT + co + 1) * OH + oy) * OW];
#pragma unroll
        for (int ix = 0; ix < 4; ix++) {
            const int ox = ox0 + px0 + ix;
            if (ox >= OW) continue;
            float v0, v1;
            unpack2(acc2[iy][ix], v0, v1);
            yp0[ox] = v0 + bv0;
            yp1[ox] = v1 + bv1;
        }
    }
}

// ---------------------------------------------------------------------------
// Kernel 2: per-(batch, group) mean / rstd, float4 vectorized, fixed tree.
// ---------------------------------------------------------------------------
__global__ __launch_bounds__(256)
void gn_stats_kernel()
{
    const int bg = blockIdx.x;
    const int N  = CPG * OH * OW;                  // 127008
    const float4* __restrict__ p4 =
        reinterpret_cast<const float4*>(g_y + (size_t)bg * N);
    const int N4 = N / 4;

    const int tid = threadIdx.x;
    float s = 0.f, ss = 0.f;
    for (int i = tid; i < N4; i += 256) {
        float4 v = p4[i];
        s  += v.x + v.y + v.z + v.w;
        ss += v.x * v.x + v.y * v.y + v.z * v.z + v.w * v.w;
    }
    __shared__ float sh_s[256];
    __shared__ float sh_q[256];
    sh_s[tid] = s;
    sh_q[tid] = ss;
    __syncthreads();
    for (int off = 128; off > 0; off >>= 1) {
        if (tid < off) {
            sh_s[tid] += sh_s[tid + off];
            sh_q[tid] += sh_q[tid + off];
        }
        __syncthreads();
    }
    if (tid == 0) {
        float mean = sh_s[0] / (float)N;
        float var  = sh_q[0] / (float)N - mean * mean;
        g_mean[bg] = mean;
        g_rstd[bg] = rsqrtf(var + GN_EPS);
    }
}

// ---------------------------------------------------------------------------
// Kernel 3: normalize + affine + scale + 2x2 maxpool + clip [0,1]
// ---------------------------------------------------------------------------
__global__ __launch_bounds__(256)
void fuse_out_kernel(const float* __restrict__ gw,
                     const float* __restrict__ gb,
                     const float* __restrict__ sc,
                     float* __restrict__ out)
{
    const int total = BB * COUT * PH * PW;
    int idx = blockIdx.x * blockDim.x + threadIdx.x;
    if (idx >= total) return;

    int px = idx % PW;
    int t  = idx / PW;
    int py = t % PH;  t /= PH;
    int c  = t % COUT;
    int b  = t / COUT;

    const int bg     = b * NG + (c >> 3);
    const float mean = g_mean[bg];
    const float rstd = g_rstd[bg];
    const float gwc  = gw[c];
    const float scc  = sc[c];
    const float a    = rstd * gwc * scc;
    const float bb   = (gb[c] - mean * rstd * gwc) * scc;

    const float* yp = g_y + (((size_t)b * COUT + c) * OH + 2 * py) * OW + 2 * px;
    float v0 = fmaf(a, yp[0],      bb);
    float v1 = fmaf(a, yp[1],      bb);
    float v2 = fmaf(a, yp[OW],     bb);
    float v3 = fmaf(a, yp[OW + 1], bb);
    float m = fmaxf(fmaxf(v0, v1), fmaxf(v2, v3));
    out[idx] = fminf(fmaxf(m, 0.0f), 1.0f);
}

// ---------------------------------------------------------------------------
extern "C" void kernel_launch(void* const* d_in, const int* in_sizes, int n_in,
                              void* d_out, int out_size)
{
    const float* x      = (const float*)d_in[0];   // [32,64,128,128]
    const float* conv_w = (const float*)d_in[1];   // [128,64,3,3]
    const float* conv_b = (const float*)d_in[2];   // [128]
    const float* gn_w   = (const float*)d_in[3];   // [128]
    const float* gn_b   = (const float*)d_in[4];   // [128]
    const float* scale  = (const float*)d_in[5];   // [128,1,1]
    float* out = (float*)d_out;                    // [32,128,63,63]

    dim3 cgrid(8, 8, BB * (COUT / CO_T));
    conv_kernel<<<cgrid, 256>>>(x, conv_w, conv_b);

    gn_stats_kernel<<<BB * NG, 256>>>();

    const int total = BB * COUT * PH * PW;
    fuse_out_kernel<<<(total + 255) / 256, 256>>>(gn_w, gn_b, scale, out);
}

// round 7
// speedup vs baseline: 2.2059x; 2.2059x over previous
#include <cuda_runtime.h>

// Problem constants
#define BB    32
#define CIN   64
#define HIN   128
#define WIN   128
#define COUT  128
#define OH    126
#define OW    126
#define NG    16
#define CPG   8
#define PH    63
#define PW    63
#define GN_EPS 1e-5f

typedef unsigned long long u64;

__device__ float g_y[(size_t)BB * COUT * OH * OW];
__device__ float g_mean[BB * NG];
__device__ float g_rstd[BB * NG];

__device__ __forceinline__ u64 pack2(float lo, float hi) {
    u64 r;
    asm("mov.b64 %0, {%1, %2};" : "=l"(r) : "f"(lo), "f"(hi));
    return r;
}
__device__ __forceinline__ u64 ffma2(u64 a, u64 b, u64 c) {
    u64 d;
    asm("fma.rn.f32x2 %0, %1, %2, %3;" : "=l"(d) : "l"(a), "l"(b), "l"(c));
    return d;
}
__device__ __forceinline__ void unpack2(u64 v, float& lo, float& hi) {
    asm("mov.b64 {%0, %1}, %2;" : "=f"(lo), "=f"(hi) : "l"(v));
}

// ---------------------------------------------------------------------------
// Kernel 1: direct 3x3 conv (VALID) + bias -> g_y
// Block: 32 output channels x 16x16 pixel tile, 256 threads.
// Thread: 4 channels (two f32x2 channel-pairs) x 4x2 pixels = 32 outputs.
// Warp: one channel-quad x 32 positions -> weight LDS.64 is exact broadcast.
// x tile plain (non-duplicated) in smem; broadcast pair (x,x) = 1 mov.b64,
// reused across both channel pairs and all taps.
// ---------------------------------------------------------------------------
#define CO_T 32
#define CI_T 8
#define TILE 16
#define XROW 20   // padded row: 80B, keeps float4 loads aligned

__global__ __launch_bounds__(256, 2)
void conv_kernel(const float* __restrict__ x,
                 const float* __restrict__ w,
                 const float* __restrict__ bias)
{
    __shared__ __align__(16) float  xs[CI_T][18][XROW];
    __shared__ __align__(16) float2 ws2[CO_T / 2][CI_T][9];   // channel pairs

    const int bx  = blockIdx.x;            // 8 tiles in x
    const int by  = blockIdx.y;            // 8 tiles in y
    const int bz  = blockIdx.z;            // b * 4 + co_group
    const int b   = bz >> 2;
    const int co0 = (bz & 3) * CO_T;
    const int oy0 = by * TILE;
    const int ox0 = bx * TILE;

    const int tid = threadIdx.x;
    const int cq  = tid >> 5;              // channel quad 0..7 (uniform per warp)
    const int pos = tid & 31;
    const int px0 = (pos & 3) * 4;         // 0,4,8,12
    const int py0 = (pos >> 2) * 2;        // 0,2,...,14

    u64 acc2[2][8];                        // [pair][iy*4+ix]
#pragma unroll
    for (int p = 0; p < 2; p++)
#pragma unroll
        for (int j = 0; j < 8; j++) acc2[p][j] = 0ull;

    for (int ci0 = 0; ci0 < CIN; ci0 += CI_T) {
        // ---- x tile: 8cc x 18 rows x 5 float4 ----
#pragma unroll
        for (int it = 0; it < 3; it++) {
            int idx = tid + it * 256;
            if (idx < CI_T * 18 * 5) {
                int cc  = idx / 90;
                int rem = idx - cc * 90;
                int r   = rem / 5;
                int q   = rem - r * 5;
                int gy  = oy0 + r;
                int gx  = ox0 + 4 * q;
                float4 v = make_float4(0.f, 0.f, 0.f, 0.f);
                if (gy < HIN && gx < WIN)
                    v = *reinterpret_cast<const float4*>(
                        &x[(((size_t)b * CIN + ci0 + cc) * HIN + gy) * WIN + gx]);
                *reinterpret_cast<float4*>(&xs[cc][r][4 * q]) = v;
            }
        }
        // ---- weights: 16 channel pairs x 8cc x 9 taps ----
#pragma unroll
        for (int it = 0; it < 5; it++) {
            int idx = tid + it * 256;
            if (idx < (CO_T / 2) * CI_T * 9) {
                int p   = idx / 72;
                int rem = idx - p * 72;
                int cc  = rem / 9;
                int k   = rem - cc * 9;
                int co  = co0 + 2 * p;
                float w0 = w[((size_t)co       * CIN + ci0 + cc) * 9 + k];
                float w1 = w[((size_t)(co + 1) * CIN + ci0 + cc) * 9 + k];
                ws2[p][cc][k] = make_float2(w0, w1);
            }
        }
        __syncthreads();

#pragma unroll
        for (int cc = 0; cc < CI_T; cc++) {
            u64 wp[2][9];
#pragma unroll
            for (int k = 0; k < 9; k++) {
                wp[0][k] = *reinterpret_cast<const u64*>(&ws2[2 * cq    ][cc][k]);
                wp[1][k] = *reinterpret_cast<const u64*>(&ws2[2 * cq + 1][cc][k]);
            }

#pragma unroll
            for (int rl = 0; rl < 4; rl++) {
                const float* rowp = &xs[cc][py0 + rl][px0];
                const float4 f = *reinterpret_cast<const float4*>(rowp);
                const float2 g = *reinterpret_cast<const float2*>(rowp + 4);
                u64 X[6];
                X[0] = pack2(f.x, f.x);
                X[1] = pack2(f.y, f.y);
                X[2] = pack2(f.z, f.z);
                X[3] = pack2(f.w, f.w);
                X[4] = pack2(g.x, g.x);
                X[5] = pack2(g.y, g.y);
#pragma unroll
                for (int iy = 0; iy < 2; iy++) {
                    const int kr = rl - iy;
                    if (kr < 0 || kr > 2) continue;
#pragma unroll
                    for (int kc = 0; kc < 3; kc++) {
#pragma unroll
                        for (int p = 0; p < 2; p++) {
                            const u64 wv = wp[p][kr * 3 + kc];
                            acc2[p][iy * 4 + 0] = ffma2(X[0 + kc], wv, acc2[p][iy * 4 + 0]);
                            acc2[p][iy * 4 + 1] = ffma2(X[1 + kc], wv, acc2[p][iy * 4 + 1]);
                            acc2[p][iy * 4 + 2] = ffma2(X[2 + kc], wv, acc2[p][iy * 4 + 2]);
                            acc2[p][iy * 4 + 3] = ffma2(X[3 + kc], wv, acc2[p][iy * 4 + 3]);
                        }
                    }
                }
            }
        }
        __syncthreads();
    }

    const int co = co0 + 4 * cq;
#pragma unroll
    for (int p = 0; p < 2; p++) {
        const int   c0  = co + 2 * p;
        const float bv0 = bias[c0];
        const float bv1 = bias[c0 + 1];
#pragma unroll
        for (int iy = 0; iy < 2; iy++) {
            const int oy = oy0 + py0 + iy;
            if (oy >= OH) continue;
            float* yp0 = &g_y[(((size_t)b * COUT + c0)     * OH + oy) * OW];
            float* yp1 = &g_y[(((size_t)b * COUT + c0 + 1) * OH + oy) * OW];
#pragma unroll
            for (int ix = 0; ix < 4; ix++) {
                const int ox = ox0 + px0 + ix;
                if (ox >= OW) continue;
                float v0, v1;
                unpack2(acc2[p][iy * 4 + ix], v0, v1);
                yp0[ox] = v0 + bv0;
                yp1[ox] = v1 + bv1;
            }
        }
    }
}

// ---------------------------------------------------------------------------
// Kernel 2: per-(batch, group) mean / rstd, float4 vectorized, fixed tree.
// ---------------------------------------------------------------------------
__global__ __launch_bounds__(256)
void gn_stats_kernel()
{
    const int bg = blockIdx.x;
    const int N  = CPG * OH * OW;                  // 127008
    const float4* __restrict__ p4 =
        reinterpret_cast<const float4*>(g_y + (size_t)bg * N);
    const int N4 = N / 4;

    const int tid = threadIdx.x;
    float s = 0.f, ss = 0.f;
    for (int i = tid; i < N4; i += 256) {
        float4 v = p4[i];
        s  += v.x + v.y + v.z + v.w;
        ss += v.x * v.x + v.y * v.y + v.z * v.z + v.w * v.w;
    }
    __shared__ float sh_s[256];
    __shared__ float sh_q[256];
    sh_s[tid] = s;
    sh_q[tid] = ss;
    __syncthreads();
    for (int off = 128; off > 0; off >>= 1) {
        if (tid < off) {
            sh_s[tid] += sh_s[tid + off];
            sh_q[tid] += sh_q[tid + off];
        }
        __syncthreads();
    }
    if (tid == 0) {
        float mean = sh_s[0] / (float)N;
        float var  = sh_q[0] / (float)N - mean * mean;
        g_mean[bg] = mean;
        g_rstd[bg] = rsqrtf(var + GN_EPS);
    }
}

// ---------------------------------------------------------------------------
// Kernel 3: normalize + affine + scale + 2x2 maxpool + clip [0,1]
// ---------------------------------------------------------------------------
__global__ __launch_bounds__(256)
void fuse_out_kernel(const float* __restrict__ gw,
                     const float* __restrict__ gb,
                     const float* __restrict__ sc,
                     float* __restrict__ out)
{
    const int total = BB * COUT * PH * PW;
    int idx = blockIdx.x * blockDim.x + threadIdx.x;
    if (idx >= total) return;

    int px = idx % PW;
    int t  = idx / PW;
    int py = t % PH;  t /= PH;
    int c  = t % COUT;
    int b  = t / COUT;

    const int bg     = b * NG + (c >> 3);
    const float mean = g_mean[bg];
    const float rstd = g_rstd[bg];
    const float gwc  = gw[c];
    const float scc  = sc[c];
    const float a    = rstd * gwc * scc;
    const float bb   = (gb[c] - mean * rstd * gwc) * scc;

    const float* yp = g_y + (((size_t)b * COUT + c) * OH + 2 * py) * OW + 2 * px;
    float v0 = fmaf(a, yp[0],      bb);
    float v1 = fmaf(a, yp[1],      bb);
    float v2 = fmaf(a, yp[OW],     bb);
    float v3 = fmaf(a, yp[OW + 1], bb);
    float m = fmaxf(fmaxf(v0, v1), fmaxf(v2, v3));
    out[idx] = fminf(fmaxf(m, 0.0f), 1.0f);
}

// ---------------------------------------------------------------------------
extern "C" void kernel_launch(void* const* d_in, const int* in_sizes, int n_in,
                              void* d_out, int out_size)
{
    const float* x      = (const float*)d_in[0];   // [32,64,128,128]
    const float* conv_w = (const float*)d_in[1];   // [128,64,3,3]
    const float* conv_b = (const float*)d_in[2];   // [128]
    const float* gn_w   = (const float*)d_in[3];   // [128]
    const float* gn_b   = (const float*)d_in[4];   // [128]
    const float* scale  = (const float*)d_in[5];   // [128,1,1]
    float* out = (float*)d_out;                    // [32,128,63,63]

    dim3 cgrid(8, 8, BB * (COUT / CO_T));
    conv_kernel<<<cgrid, 256>>>(x, conv_w, conv_b);

    gn_stats_kernel<<<BB * NG, 256>>>();

    const int total = BB * COUT * PH * PW;
    fuse_out_kernel<<<(total + 255) / 256, 256>>>(gn_w, gn_b, scale, out);
}

// round 11
// speedup vs baseline: 2.8889x; 1.3096x over previous
#include <cuda_runtime.h>
#include <cuda_bf16.h>
#include <cstdint>

// Problem constants
#define BB    32
#define CIN   64
#define HIN   128
#define WIN   128
#define COUT  128
#define OH    126
#define OW    126
#define NG    16
#define CPG   8
#define PH    63
#define PW    63
#define GN_EPS 1e-5f

#define XT_ROWS (BB * HIN * WIN)     // 524288 flat pixel rows
#define XT_PAD  256
#define XT_TOT  (XT_ROWS + XT_PAD)

// Scratch
__device__ float g_y[(size_t)BB * COUT * OH * OW];
__device__ float g_mean[BB * NG];
__device__ float g_rstd[BB * NG];
__device__ __nv_bfloat16 g_xt_hi[(size_t)XT_TOT * CIN];   // NHWC bf16 hi (128B/pixel)
__device__ __nv_bfloat16 g_xt_lo[(size_t)XT_TOT * CIN];   // NHWC bf16 lo
__device__ __nv_bfloat16 g_wa_hi[9 * COUT * CIN];         // per-tap W hi [tap][co][ci]
__device__ __nv_bfloat16 g_wa_lo[9 * COUT * CIN];

// ---------------- low-level helpers ----------------------------------------
__device__ __forceinline__ uint32_t smem_u32(const void* p) {
    uint32_t a;
    asm("{ .reg .u64 t; cvta.to.shared.u64 t, %1; cvt.u32.u64 %0, t; }"
        : "=r"(a) : "l"(p));
    return a;
}
__device__ __forceinline__ void cp_async16(uint32_t dst, const void* src) {
    asm volatile("cp.async.cg.shared.global [%0], [%1], 16;"
                 :: "r"(dst), "l"(src) : "memory");
}
#define CP_COMMIT() asm volatile("cp.async.commit_group;" ::: "memory")
#define CP_WAIT0()  asm volatile("cp.async.wait_group 0;" ::: "memory")

__device__ __forceinline__ void ldmx4(uint32_t& r0, uint32_t& r1,
                                      uint32_t& r2, uint32_t& r3, uint32_t addr) {
    asm volatile("ldmatrix.sync.aligned.m8n8.x4.shared.b16 {%0,%1,%2,%3}, [%4];"
                 : "=r"(r0), "=r"(r1), "=r"(r2), "=r"(r3) : "r"(addr));
}
__device__ __forceinline__ void mma16816(float* c, const uint32_t* a,
                                         uint32_t b0, uint32_t b1) {
    asm volatile(
        "mma.sync.aligned.m16n8k16.row.col.f32.bf16.bf16.f32 "
        "{%0,%1,%2,%3}, {%4,%5,%6,%7}, {%8,%9}, {%0,%1,%2,%3};"
        : "+f"(c[0]), "+f"(c[1]), "+f"(c[2]), "+f"(c[3])
        : "r"(a[0]), "r"(a[1]), "r"(a[2]), "r"(a[3]), "r"(b0), "r"(b1));
}

// ---------------- smem layout ------------------------------------------------
#define XPITCH   144                      // bytes per pixel entry (128 + pad)
#define XS_SPLIT (3 * 132 * XPITCH)       // 57024 per split
#define WS_OFF   (2 * XS_SPLIT)           // 114048
#define WSPLIT   (128 * 144)              // 18432 per split
#define WSTAGE   (2 * WSPLIT)             // 36864 per stage
#define SMEM_TOTAL (WS_OFF + 2 * WSTAGE)  // 187776

// ---------------- Prepass kernels -------------------------------------------
__global__ __launch_bounds__(256)
void prep_w_kernel(const float* __restrict__ w)
{
    int idx = blockIdx.x * 256 + threadIdx.x;          // (tap*128 + co)*64 + ci
    if (idx >= 9 * COUT * CIN) return;
    int ci  = idx & 63;
    int t2  = idx >> 6;
    int co  = t2 & 127;
    int tap = t2 >> 7;
    float v = w[((size_t)co * CIN + ci) * 9 + tap];
    __nv_bfloat16 hi = __float2bfloat16(v);
    float r = v - __bfloat162float(hi);
    g_wa_hi[idx] = hi;
    g_wa_lo[idx] = __float2bfloat16(r);
}

__global__ __launch_bounds__(256)
void prep_x_kernel(const float* __restrict__ x)
{
    __shared__ float xs[64][129];
    const int y = blockIdx.x;
    const int b = blockIdx.y;
    const int tid = threadIdx.x;
    for (int i = tid; i < 64 * 128; i += 256) {
        int ci = i >> 7;
        int xc = i & 127;
        xs[ci][xc] = x[(((size_t)b * CIN + ci) * HIN + y) * WIN + xc];
    }
    __syncthreads();
    const size_t pbase = ((size_t)(b * HIN + y)) * WIN;
    for (int j = tid; j < 64 * 128; j += 256) {
        int xc = j >> 6;
        int ci = j & 63;
        float v = xs[ci][xc];
        __nv_bfloat16 hi = __float2bfloat16(v);
        float r = v - __bfloat162float(hi);
        size_t o = (pbase + xc) * CIN + ci;
        g_xt_hi[o] = hi;
        g_xt_lo[o] = __float2bfloat16(r);
    }
}

__global__ __launch_bounds__(256)
void zero_pad_kernel()
{
    int idx = blockIdx.x * 256 + threadIdx.x;
    if (idx < XT_PAD * CIN) {
        size_t o = (size_t)XT_ROWS * CIN + idx;
        __nv_bfloat16 z = __float2bfloat16(0.f);
        g_xt_hi[o] = z;
        g_xt_lo[o] = z;
    }
}

// ---------------- Main mma.sync conv kernel ---------------------------------
// Grid (126 y, 32 b), 256 threads = 8 warps (4 m x 2 n). Warp tile 32co x 64px.
__global__ __launch_bounds__(256)
void conv_mma_kernel(const float* __restrict__ bias)
{
    extern __shared__ __align__(128) char smem[];
    const uint32_t sb = smem_u32(smem);
    const int tid  = threadIdx.x;
    const int wid  = tid >> 5;
    const int lane = tid & 31;
    const int y = blockIdx.x;
    const int b = blockIdx.y;
    const int wm = wid & 3;         // 0..3 : co block of 32
    const int wn = wid >> 2;        // 0..1 : px block of 64

    // ---- prologue: X union (both splits) + W tap 0 -> stage 0 ----
    const int rowstart = (b * HIN + y) * WIN;
    for (int i = tid; i < 6336; i += 256) {               // 2 splits*3*132*8
        int s = i / 3168;
        int r = i - s * 3168;
        int entry = r >> 3;
        int h     = r & 7;
        int yrow  = entry / 132;
        int px    = entry - yrow * 132;
        size_t p  = (size_t)(rowstart + yrow * WIN + px); // fits pad region
        const char* srcb = s ? (const char*)g_xt_lo : (const char*)g_xt_hi;
        cp_async16(sb + s * XS_SPLIT + entry * XPITCH + h * 16,
                   srcb + p * 128 + h * 16);
    }
    for (int i = tid; i < 2048; i += 256) {               // W tap0: 2 splits*128co*8
        int s  = i >> 10;
        int r  = i & 1023;
        int co = r >> 3;
        int h  = r & 7;
        const char* srcb = s ? (const char*)g_wa_lo : (const char*)g_wa_hi;
        cp_async16(sb + WS_OFF + s * WSPLIT + co * 144 + h * 16,
                   srcb + (size_t)co * 128 + h * 16);
    }
    CP_COMMIT();
    CP_WAIT0();
    __syncthreads();

    float acc[2][8][4];
#pragma unroll
    for (int i = 0; i < 2; i++)
#pragma unroll
        for (int j = 0; j < 8; j++)
#pragma unroll
            for (int k = 0; k < 4; k++) acc[i][j][k] = 0.f;

    for (int t = 0; t < 9; t++) {
        const int stage = t & 1;
        if (t + 1 < 9) {                                   // prefetch next W
            for (int i = tid; i < 2048; i += 256) {
                int s  = i >> 10;
                int r  = i & 1023;
                int co = r >> 3;
                int h  = r & 7;
                const char* srcb = s ? (const char*)g_wa_lo : (const char*)g_wa_hi;
                cp_async16(sb + WS_OFF + (stage ^ 1) * WSTAGE + s * WSPLIT + co * 144 + h * 16,
                           srcb + ((size_t)((t + 1) * 128 + co)) * 128 + h * 16);
            }
            CP_COMMIT();
        }

        const int ky = t / 3;
        const int kx = t - 3 * ky;
        const uint32_t wsb = sb + WS_OFF + stage * WSTAGE;

#pragma unroll
        for (int kc = 0; kc < 4; kc++) {
            uint32_t ah[2][4], al[2][4];
#pragma unroll
            for (int mt = 0; mt < 2; mt++) {
                uint32_t rowco = (uint32_t)(wm * 32 + mt * 16 + (lane & 15));
                uint32_t aoff  = rowco * 144 + kc * 32 + ((lane >> 4) << 4);
                ldmx4(ah[mt][0], ah[mt][1], ah[mt][2], ah[mt][3], wsb + aoff);
                ldmx4(al[mt][0], al[mt][1], al[mt][2], al[mt][3], wsb + WSPLIT + aoff);
            }
#pragma unroll
            for (int pr = 0; pr < 4; pr++) {
                int pxl = wn * 64 + pr * 16 + (lane & 7) + ((lane >> 4) << 3) + kx;
                uint32_t entry = (uint32_t)(ky * 132 + pxl);
                uint32_t boff  = entry * XPITCH + kc * 32 + (((lane >> 3) & 1) << 4);
                uint32_t bh0, bh1, bh2, bh3, bl0, bl1, bl2, bl3;
                ldmx4(bh0, bh1, bh2, bh3, sb + boff);
                ldmx4(bl0, bl1, bl2, bl3, sb + XS_SPLIT + boff);
#pragma unroll
                for (int mt = 0; mt < 2; mt++) {
                    mma16816(acc[mt][pr * 2 + 0], ah[mt], bh0, bh1);
                    mma16816(acc[mt][pr * 2 + 1], ah[mt], bh2, bh3);
                    mma16816(acc[mt][pr * 2 + 0], ah[mt], bl0, bl1);
                    mma16816(acc[mt][pr * 2 + 1], ah[mt], bl2, bl3);
                    mma16816(acc[mt][pr * 2 + 0], al[mt], bh0, bh1);
                    mma16816(acc[mt][pr * 2 + 1], al[mt], bh2, bh3);
                }
            }
        }
        CP_WAIT0();
        __syncthreads();
    }

    // ---- epilogue: accum -> smem (reuse X region) -> coalesced +bias STG ----
    float* smf = (float*)smem;                 // [128][132] fp32 = 67.6 KB
#pragma unroll
    for (int mt = 0; mt < 2; mt++)
#pragma unroll
        for (int nt = 0; nt < 8; nt++) {
            int co = wm * 32 + mt * 16 + (lane >> 2);
            int px = wn * 64 + (nt >> 1) * 16 + (nt & 1) * 8 + ((lane & 3) << 1);
            smf[co * 132 + px]           = acc[mt][nt][0];
            smf[co * 132 + px + 1]       = acc[mt][nt][1];
            smf[(co + 8) * 132 + px]     = acc[mt][nt][2];
            smf[(co + 8) * 132 + px + 1] = acc[mt][nt][3];
        }
    __syncthreads();

#pragma unroll 4
    for (int k = 0; k < 16; k++) {
        const int r = wid * 16 + k;
        const float bv = bias[r];
        float* dst = &g_y[(((size_t)b * COUT + r) * OH + y) * OW];
        const float* srow = &smf[r * 132];
#pragma unroll
        for (int j = 0; j < 4; j++) {
            const int xc = lane + 32 * j;
            if (xc < OW) dst[xc] = srow[xc] + bv;
        }
    }
}

// ---------------- GroupNorm stats -------------------------------------------
__global__ __launch_bounds__(256)
void gn_stats_kernel()
{
    const int bg = blockIdx.x;
    const int N  = CPG * OH * OW;                  // 127008
    const float4* __restrict__ p4 =
        reinterpret_cast<const float4*>(g_y + (size_t)bg * N);
    const int N4 = N / 4;

    const int tid = threadIdx.x;
    float s = 0.f, ss = 0.f;
    for (int i = tid; i < N4; i += 256) {
        float4 v = p4[i];
        s  += v.x + v.y + v.z + v.w;
        ss += v.x * v.x + v.y * v.y + v.z * v.z + v.w * v.w;
    }
    __shared__ float sh_s[256];
    __shared__ float sh_q[256];
    sh_s[tid] = s;
    sh_q[tid] = ss;
    __syncthreads();
    for (int off = 128; off > 0; off >>= 1) {
        if (tid < off) {
            sh_s[tid] += sh_s[tid + off];
            sh_q[tid] += sh_q[tid + off];
        }
        __syncthreads();
    }
    if (tid == 0) {
        float mean = sh_s[0] / (float)N;
        float var  = sh_q[0] / (float)N - mean * mean;
        g_mean[bg] = mean;
        g_rstd[bg] = rsqrtf(var + GN_EPS);
    }
}

// ---------------- Fused epilogue --------------------------------------------
__global__ __launch_bounds__(256)
void fuse_out_kernel(const float* __restrict__ gw,
                     const float* __restrict__ gb,
                     const float* __restrict__ sc,
                     float* __restrict__ out)
{
    const int total = BB * COUT * PH * PW;
    int idx = blockIdx.x * blockDim.x + threadIdx.x;
    if (idx >= total) return;

    int px = idx % PW;
    int t  = idx / PW;
    int py = t % PH;  t /= PH;
    int c  = t % COUT;
    int b  = t / COUT;

    const int bg     = b * NG + (c >> 3);
    const float mean = g_mean[bg];
    const float rstd = g_rstd[bg];
    const float gwc  = gw[c];
    const float scc  = sc[c];
    const float a    = rstd * gwc * scc;
    const float bb   = (gb[c] - mean * rstd * gwc) * scc;

    const float* yp = g_y + (((size_t)b * COUT + c) * OH + 2 * py) * OW + 2 * px;
    float v0 = fmaf(a, yp[0],      bb);
    float v1 = fmaf(a, yp[1],      bb);
    float v2 = fmaf(a, yp[OW],     bb);
    float v3 = fmaf(a, yp[OW + 1], bb);
    float m = fmaxf(fmaxf(v0, v1), fmaxf(v2, v3));
    out[idx] = fminf(fmaxf(m, 0.0f), 1.0f);
}

// ---------------------------------------------------------------------------
extern "C" void kernel_launch(void* const* d_in, const int* in_sizes, int n_in,
                              void* d_out, int out_size)
{
    const float* x      = (const float*)d_in[0];   // [32,64,128,128]
    const float* conv_w = (const float*)d_in[1];   // [128,64,3,3]
    const float* conv_b = (const float*)d_in[2];   // [128]
    const float* gn_w   = (const float*)d_in[3];   // [128]
    const float* gn_b   = (const float*)d_in[4];   // [128]
    const float* scale  = (const float*)d_in[5];   // [128,1,1]
    float* out = (float*)d_out;                    // [32,128,63,63]

    cudaFuncSetAttribute(conv_mma_kernel,
                         cudaFuncAttributeMaxDynamicSharedMemorySize, SMEM_TOTAL);

    prep_w_kernel<<<(9 * COUT * CIN + 255) / 256, 256>>>(conv_w);
    prep_x_kernel<<<dim3(HIN, BB), 256>>>(x);
    zero_pad_kernel<<<(XT_PAD * CIN + 255) / 256, 256>>>();

    conv_mma_kernel<<<dim3(OH, BB), 256, SMEM_TOTAL>>>(conv_b);

    gn_stats_kernel<<<BB * NG, 256>>>();

    const int total = BB * COUT * PH * PW;
    fuse_out_kernel<<<(total + 255) / 256, 256>>>(gn_w, gn_b, scale, out);
}

// round 12
// speedup vs baseline: 2.9834x; 1.0327x over previous
#include <cuda_runtime.h>
#include <cuda_bf16.h>
#include <cstdint>

// Problem constants
#define BB    32
#define CIN   64
#define HIN   128
#define WIN   128
#define COUT  128
#define OH    126
#define OW    126
#define NG    16
#define CPG   8
#define PH    63
#define PW    63
#define GN_EPS 1e-5f

#define XT_ROWS (BB * HIN * WIN)     // 524288 flat pixel rows
#define XT_PAD  256
#define XT_TOT  (XT_ROWS + XT_PAD)

// Scratch
__device__ float g_y[(size_t)BB * COUT * OH * OW];
__device__ float g_mean[BB * NG];
__device__ float g_rstd[BB * NG];
__device__ __nv_bfloat16 g_xt_hi[(size_t)XT_TOT * CIN];   // NHWC bf16 hi (128B/pixel)
__device__ __nv_bfloat16 g_xt_lo[(size_t)XT_TOT * CIN];   // NHWC bf16 lo
__device__ __nv_bfloat16 g_wa_hi[9 * COUT * CIN];         // per-tap W hi [tap][co][ci]
__device__ __nv_bfloat16 g_wa_lo[9 * COUT * CIN];

// ---------------- low-level helpers ----------------------------------------
__device__ __forceinline__ uint32_t smem_u32(const void* p) {
    uint32_t a;
    asm("{ .reg .u64 t; cvta.to.shared.u64 t, %1; cvt.u32.u64 %0, t; }"
        : "=r"(a) : "l"(p));
    return a;
}
__device__ __forceinline__ void cp_async16(uint32_t dst, const void* src) {
    asm volatile("cp.async.cg.shared.global [%0], [%1], 16;"
                 :: "r"(dst), "l"(src) : "memory");
}
#define CP_COMMIT() asm volatile("cp.async.commit_group;" ::: "memory")
#define CP_WAIT0()  asm volatile("cp.async.wait_group 0;" ::: "memory")

__device__ __forceinline__ void ldmx4(uint32_t& r0, uint32_t& r1,
                                      uint32_t& r2, uint32_t& r3, uint32_t addr) {
    asm volatile("ldmatrix.sync.aligned.m8n8.x4.shared.b16 {%0,%1,%2,%3}, [%4];"
                 : "=r"(r0), "=r"(r1), "=r"(r2), "=r"(r3) : "r"(addr));
}
__device__ __forceinline__ void mma16816(float* c, const uint32_t* a,
                                         uint32_t b0, uint32_t b1) {
    asm volatile(
        "mma.sync.aligned.m16n8k16.row.col.f32.bf16.bf16.f32 "
        "{%0,%1,%2,%3}, {%4,%5,%6,%7}, {%8,%9}, {%0,%1,%2,%3};"
        : "+f"(c[0]), "+f"(c[1]), "+f"(c[2]), "+f"(c[3])
        : "r"(a[0]), "r"(a[1]), "r"(a[2]), "r"(a[3]), "r"(b0), "r"(b1));
}

// ---------------- smem layout ------------------------------------------------
#define XPITCH   144                      // bytes per pixel entry (128 + pad)
#define XS_SPLIT (3 * 132 * XPITCH)       // 57024 per split
#define WS_OFF   (2 * XS_SPLIT)           // 114048
#define WSPLIT   (128 * 144)              // 18432 per split
#define WSTAGE   (2 * WSPLIT)             // 36864 per stage
#define SMEM_TOTAL (WS_OFF + 2 * WSTAGE)  // 187776

// ---------------- Prepass kernels -------------------------------------------
__global__ __launch_bounds__(256)
void prep_w_kernel(const float* __restrict__ w)
{
    int idx = blockIdx.x * 256 + threadIdx.x;          // (tap*128 + co)*64 + ci
    if (idx >= 9 * COUT * CIN) return;
    int ci  = idx & 63;
    int t2  = idx >> 6;
    int co  = t2 & 127;
    int tap = t2 >> 7;
    float v = w[((size_t)co * CIN + ci) * 9 + tap];
    __nv_bfloat16 hi = __float2bfloat16(v);
    float r = v - __bfloat162float(hi);
    g_wa_hi[idx] = hi;
    g_wa_lo[idx] = __float2bfloat16(r);
}

__global__ __launch_bounds__(256)
void prep_x_kernel(const float* __restrict__ x)
{
    __shared__ float xs[64][129];
    const int y = blockIdx.x;
    const int b = blockIdx.y;
    const int tid = threadIdx.x;
    for (int i = tid; i < 64 * 128; i += 256) {
        int ci = i >> 7;
        int xc = i & 127;
        xs[ci][xc] = x[(((size_t)b * CIN + ci) * HIN + y) * WIN + xc];
    }
    __syncthreads();
    const size_t pbase = ((size_t)(b * HIN + y)) * WIN;
    for (int j = tid; j < 64 * 128; j += 256) {
        int xc = j >> 6;
        int ci = j & 63;
        float v = xs[ci][xc];
        __nv_bfloat16 hi = __float2bfloat16(v);
        float r = v - __bfloat162float(hi);
        size_t o = (pbase + xc) * CIN + ci;
        g_xt_hi[o] = hi;
        g_xt_lo[o] = __float2bfloat16(r);
    }
}

__global__ __launch_bounds__(256)
void zero_pad_kernel()
{
    int idx = blockIdx.x * 256 + threadIdx.x;
    if (idx < XT_PAD * CIN) {
        size_t o = (size_t)XT_ROWS * CIN + idx;
        __nv_bfloat16 z = __float2bfloat16(0.f);
        g_xt_hi[o] = z;
        g_xt_lo[o] = z;
    }
}

// ---------------- Main mma.sync conv kernel ---------------------------------
// Grid (126 y, 32 b), 256 threads = 8 warps (4 m x 2 n). Warp tile 32co x 64px.
// Per k-chunk: ALL A (hi+lo) and ALL B (hi+lo, 4 n-pairs) fragments loaded
// first, then 48 MMAs ordered combo->pr->mt so same-accumulator reuse
// distance is 16 MMAs (covers HMMA accumulate latency even at 2 warps/SMSP).
__global__ __launch_bounds__(256)
void conv_mma_kernel(const float* __restrict__ bias)
{
    extern __shared__ __align__(128) char smem[];
    const uint32_t sb = smem_u32(smem);
    const int tid  = threadIdx.x;
    const int wid  = tid >> 5;
    const int lane = tid & 31;
    const int y = blockIdx.x;
    const int b = blockIdx.y;
    const int wm = wid & 3;         // 0..3 : co block of 32
    const int wn = wid >> 2;        // 0..1 : px block of 64

    // ---- prologue: X union (both splits) + W tap 0 -> stage 0 ----
    const int rowstart = (b * HIN + y) * WIN;
    for (int i = tid; i < 6336; i += 256) {               // 2 splits*3*132*8
        int s = i / 3168;
        int r = i - s * 3168;
        int entry = r >> 3;
        int h     = r & 7;
        int yrow  = entry / 132;
        int px    = entry - yrow * 132;
        size_t p  = (size_t)(rowstart + yrow * WIN + px); // fits pad region
        const char* srcb = s ? (const char*)g_xt_lo : (const char*)g_xt_hi;
        cp_async16(sb + s * XS_SPLIT + entry * XPITCH + h * 16,
                   srcb + p * 128 + h * 16);
    }
    for (int i = tid; i < 2048; i += 256) {               // W tap0: 2 splits*128co*8
        int s  = i >> 10;
        int r  = i & 1023;
        int co = r >> 3;
        int h  = r & 7;
        const char* srcb = s ? (const char*)g_wa_lo : (const char*)g_wa_hi;
        cp_async16(sb + WS_OFF + s * WSPLIT + co * 144 + h * 16,
                   srcb + (size_t)co * 128 + h * 16);
    }
    CP_COMMIT();
    CP_WAIT0();
    __syncthreads();

    float acc[2][8][4];
#pragma unroll
    for (int i = 0; i < 2; i++)
#pragma unroll
        for (int j = 0; j < 8; j++)
#pragma unroll
            for (int k = 0; k < 4; k++) acc[i][j][k] = 0.f;

    for (int t = 0; t < 9; t++) {
        const int stage = t & 1;
        if (t + 1 < 9) {                                   // prefetch next W
            for (int i = tid; i < 2048; i += 256) {
                int s  = i >> 10;
                int r  = i & 1023;
                int co = r >> 3;
                int h  = r & 7;
                const char* srcb = s ? (const char*)g_wa_lo : (const char*)g_wa_hi;
                cp_async16(sb + WS_OFF + (stage ^ 1) * WSTAGE + s * WSPLIT + co * 144 + h * 16,
                           srcb + ((size_t)((t + 1) * 128 + co)) * 128 + h * 16);
            }
            CP_COMMIT();
        }

        const int ky = t / 3;
        const int kx = t - 3 * ky;
        const uint32_t wsb = sb + WS_OFF + stage * WSTAGE;

#pragma unroll
        for (int kc = 0; kc < 4; kc++) {
            // ---- all A fragments (hi+lo) : 4 ldmatrix.x4 ----
            uint32_t ah[2][4], al[2][4];
#pragma unroll
            for (int mt = 0; mt < 2; mt++) {
                uint32_t rowco = (uint32_t)(wm * 32 + mt * 16 + (lane & 15));
                uint32_t aoff  = rowco * 144 + kc * 32 + ((lane >> 4) << 4);
                ldmx4(ah[mt][0], ah[mt][1], ah[mt][2], ah[mt][3], wsb + aoff);
                ldmx4(al[mt][0], al[mt][1], al[mt][2], al[mt][3], wsb + WSPLIT + aoff);
            }
            // ---- all B fragments (hi+lo, 4 n-pairs) : 8 ldmatrix.x4 ----
            uint32_t bh[4][4], bl[4][4];
#pragma unroll
            for (int pr = 0; pr < 4; pr++) {
                int pxl = wn * 64 + pr * 16 + (lane & 7) + ((lane >> 4) << 3) + kx;
                uint32_t entry = (uint32_t)(ky * 132 + pxl);
                uint32_t boff  = entry * XPITCH + kc * 32 + (((lane >> 3) & 1) << 4);
                ldmx4(bh[pr][0], bh[pr][1], bh[pr][2], bh[pr][3], sb + boff);
                ldmx4(bl[pr][0], bl[pr][1], bl[pr][2], bl[pr][3],
                      sb + XS_SPLIT + boff);
            }
            // ---- 48 MMAs, combo-major: reuse distance = 16 ----
#pragma unroll
            for (int pr = 0; pr < 4; pr++)
#pragma unroll
                for (int mt = 0; mt < 2; mt++) {
                    mma16816(acc[mt][pr * 2 + 0], ah[mt], bh[pr][0], bh[pr][1]);
                    mma16816(acc[mt][pr * 2 + 1], ah[mt], bh[pr][2], bh[pr][3]);
                }
#pragma unroll
            for (int pr = 0; pr < 4; pr++)
#pragma unroll
                for (int mt = 0; mt < 2; mt++) {
                    mma16816(acc[mt][pr * 2 + 0], ah[mt], bl[pr][0], bl[pr][1]);
                    mma16816(acc[mt][pr * 2 + 1], ah[mt], bl[pr][2], bl[pr][3]);
                }
#pragma unroll
            for (int pr = 0; pr < 4; pr++)
#pragma unroll
                for (int mt = 0; mt < 2; mt++) {
                    mma16816(acc[mt][pr * 2 + 0], al[mt], bh[pr][0], bh[pr][1]);
                    mma16816(acc[mt][pr * 2 + 1], al[mt], bh[pr][2], bh[pr][3]);
                }
        }
        CP_WAIT0();
        __syncthreads();
    }

    // ---- epilogue: accum -> smem (reuse X region) -> coalesced +bias STG ----
    float* smf = (float*)smem;                 // [128][132] fp32 = 67.6 KB
#pragma unroll
    for (int mt = 0; mt < 2; mt++)
#pragma unroll
        for (int nt = 0; nt < 8; nt++) {
            int co = wm * 32 + mt * 16 + (lane >> 2);
            int px = wn * 64 + (nt >> 1) * 16 + (nt & 1) * 8 + ((lane & 3) << 1);
            smf[co * 132 + px]           = acc[mt][nt][0];
            smf[co * 132 + px + 1]       = acc[mt][nt][1];
            smf[(co + 8) * 132 + px]     = acc[mt][nt][2];
            smf[(co + 8) * 132 + px + 1] = acc[mt][nt][3];
        }
    __syncthreads();

#pragma unroll 4
    for (int k = 0; k < 16; k++) {
        const int r = wid * 16 + k;
        const float bv = bias[r];
        float* dst = &g_y[(((size_t)b * COUT + r) * OH + y) * OW];
        const float* srow = &smf[r * 132];
#pragma unroll
        for (int j = 0; j < 4; j++) {
            const int xc = lane + 32 * j;
            if (xc < OW) dst[xc] = srow[xc] + bv;
        }
    }
}

// ---------------- GroupNorm stats -------------------------------------------
__global__ __launch_bounds__(256)
void gn_stats_kernel()
{
    const int bg = blockIdx.x;
    const int N  = CPG * OH * OW;                  // 127008
    const float4* __restrict__ p4 =
        reinterpret_cast<const float4*>(g_y + (size_t)bg * N);
    const int N4 = N / 4;

    const int tid = threadIdx.x;
    float s = 0.f, ss = 0.f;
    for (int i = tid; i < N4; i += 256) {
        float4 v = p4[i];
        s  += v.x + v.y + v.z + v.w;
        ss += v.x * v.x + v.y * v.y + v.z * v.z + v.w * v.w;
    }
    __shared__ float sh_s[256];
    __shared__ float sh_q[256];
    sh_s[tid] = s;
    sh_q[tid] = ss;
    __syncthreads();
    for (int off = 128; off > 0; off >>= 1) {
        if (tid < off) {
            sh_s[tid] += sh_s[tid + off];
            sh_q[tid] += sh_q[tid + off];
        }
        __syncthreads();
    }
    if (tid == 0) {
        float mean = sh_s[0] / (float)N;
        float var  = sh_q[0] / (float)N - mean * mean;
        g_mean[bg] = mean;
        g_rstd[bg] = rsqrtf(var + GN_EPS);
    }
}

// ---------------- Fused epilogue --------------------------------------------
__global__ __launch_bounds__(256)
void fuse_out_kernel(const float* __restrict__ gw,
                     const float* __restrict__ gb,
                     const float* __restrict__ sc,
                     float* __restrict__ out)
{
    const int total = BB * COUT * PH * PW;
    int idx = blockIdx.x * blockDim.x + threadIdx.x;
    if (idx >= total) return;

    int px = idx % PW;
    int t  = idx / PW;
    int py = t % PH;  t /= PH;
    int c  = t % COUT;
    int b  = t / COUT;

    const int bg     = b * NG + (c >> 3);
    const float mean = g_mean[bg];
    const float rstd = g_rstd[bg];
    const float gwc  = gw[c];
    const float scc  = sc[c];
    const float a    = rstd * gwc * scc;
    const float bb   = (gb[c] - mean * rstd * gwc) * scc;

    const float* yp = g_y + (((size_t)b * COUT + c) * OH + 2 * py) * OW + 2 * px;
    float v0 = fmaf(a, yp[0],      bb);
    float v1 = fmaf(a, yp[1],      bb);
    float v2 = fmaf(a, yp[OW],     bb);
    float v3 = fmaf(a, yp[OW + 1], bb);
    float m = fmaxf(fmaxf(v0, v1), fmaxf(v2, v3));
    out[idx] = fminf(fmaxf(m, 0.0f), 1.0f);
}

// ---------------------------------------------------------------------------
extern "C" void kernel_launch(void* const* d_in, const int* in_sizes, int n_in,
                              void* d_out, int out_size)
{
    const float* x      = (const float*)d_in[0];   // [32,64,128,128]
    const float* conv_w = (const float*)d_in[1];   // [128,64,3,3]
    const float* conv_b = (const float*)d_in[2];   // [128]
    const float* gn_w   = (const float*)d_in[3];   // [128]
    const float* gn_b   = (const float*)d_in[4];   // [128]
    const float* scale  = (const float*)d_in[5];   // [128,1,1]
    float* out = (float*)d_out;                    // [32,128,63,63]

    cudaFuncSetAttribute(conv_mma_kernel,
                         cudaFuncAttributeMaxDynamicSharedMemorySize, SMEM_TOTAL);

    prep_w_kernel<<<(9 * COUT * CIN + 255) / 256, 256>>>(conv_w);
    prep_x_kernel<<<dim3(HIN, BB), 256>>>(x);
    zero_pad_kernel<<<(XT_PAD * CIN + 255) / 256, 256>>>();

    conv_mma_kernel<<<dim3(OH, BB), 256, SMEM_TOTAL>>>(conv_b);

    gn_stats_kernel<<<BB * NG, 256>>>();

    const int total = BB * COUT * PH * PW;
    fuse_out_kernel<<<(total + 255) / 256, 256>>>(gn_w, gn_b, scale, out);
}

// round 14
// speedup vs baseline: 4.0364x; 1.3530x over previous
#include <cuda_runtime.h>
#include <cuda_bf16.h>
#include <cstdint>

// Problem constants
#define BB    32
#define CIN   64
#define HIN   128
#define WIN   128
#define COUT  128
#define OH    126
#define OW    126
#define NG    16
#define CPG   8
#define PH    63
#define PW    63
#define GN_EPS 1e-5f

#define XT_ROWS (BB * HIN * WIN)     // 524288 flat pixel rows
#define XT_PAD  256
#define XT_TOT  (XT_ROWS + XT_PAD)

// Scratch
__device__ float g_y[(size_t)BB * COUT * OH * OW];
__device__ float g_mean[BB * NG];
__device__ float g_rstd[BB * NG];
__device__ __nv_bfloat16 g_xt_hi[(size_t)XT_TOT * CIN];   // NHWC bf16 hi (128B/pixel)
__device__ __nv_bfloat16 g_xt_lo[(size_t)XT_TOT * CIN];   // NHWC bf16 lo
__device__ __nv_bfloat16 g_wa_hi[9 * COUT * CIN];         // per-tap W hi [tap][co][ci]
__device__ __nv_bfloat16 g_wa_lo[9 * COUT * CIN];

// ---------------- low-level helpers ----------------------------------------
__device__ __forceinline__ uint32_t smem_u32(const void* p) {
    uint32_t a;
    asm("{ .reg .u64 t; cvta.to.shared.u64 t, %1; cvt.u32.u64 %0, t; }"
        : "=r"(a) : "l"(p));
    return a;
}
__device__ __forceinline__ void cp_async16(uint32_t dst, const void* src) {
    asm volatile("cp.async.cg.shared.global [%0], [%1], 16;"
                 :: "r"(dst), "l"(src) : "memory");
}
#define CP_COMMIT() asm volatile("cp.async.commit_group;" ::: "memory")
#define CP_WAIT0()  asm volatile("cp.async.wait_group 0;" ::: "memory")

__device__ __forceinline__ void ldmx4(uint32_t& r0, uint32_t& r1,
                                      uint32_t& r2, uint32_t& r3, uint32_t addr) {
    asm volatile("ldmatrix.sync.aligned.m8n8.x4.shared.b16 {%0,%1,%2,%3}, [%4];"
                 : "=r"(r0), "=r"(r1), "=r"(r2), "=r"(r3) : "r"(addr));
}
__device__ __forceinline__ void mma16816(float* c, const uint32_t* a,
                                         uint32_t b0, uint32_t b1) {
    asm volatile(
        "mma.sync.aligned.m16n8k16.row.col.f32.bf16.bf16.f32 "
        "{%0,%1,%2,%3}, {%4,%5,%6,%7}, {%8,%9}, {%0,%1,%2,%3};"
        : "+f"(c[0]), "+f"(c[1]), "+f"(c[2]), "+f"(c[3])
        : "r"(a[0]), "r"(a[1]), "r"(a[2]), "r"(a[3]), "r"(b0), "r"(b1));
}

// ---------------- smem layout (64-px CTA) -----------------------------------
#define XPITCH   144                      // bytes per pixel entry (128 + pad)
#define XENT     68                       // entries per y-row (64+2 used, pad 68)
#define XS_SPLIT (3 * XENT * XPITCH)      // 29376 per split
#define WS_OFF   (2 * XS_SPLIT)           // 58752
#define WSPLIT   (128 * 144)              // 18432 per split
#define SMEM_TOTAL (WS_OFF + 2 * WSPLIT)  // 95616  -> 2 CTAs / SM

// ---------------- Prepass kernels -------------------------------------------
__global__ __launch_bounds__(256)
void prep_w_kernel(const float* __restrict__ w)
{
    int idx = blockIdx.x * 256 + threadIdx.x;          // (tap*128 + co)*64 + ci
    if (idx >= 9 * COUT * CIN) return;
    int ci  = idx & 63;
    int t2  = idx >> 6;
    int co  = t2 & 127;
    int tap = t2 >> 7;
    float v = w[((size_t)co * CIN + ci) * 9 + tap];
    __nv_bfloat16 hi = __float2bfloat16(v);
    float r = v - __bfloat162float(hi);
    g_wa_hi[idx] = hi;
    g_wa_lo[idx] = __float2bfloat16(r);
}

__global__ __launch_bounds__(256)
void prep_x_kernel(const float* __restrict__ x)
{
    __shared__ float xs[64][129];
    const int y = blockIdx.x;
    const int b = blockIdx.y;
    const int tid = threadIdx.x;
    for (int i = tid; i < 64 * 128; i += 256) {
        int ci = i >> 7;
        int xc = i & 127;
        xs[ci][xc] = x[(((size_t)b * CIN + ci) * HIN + y) * WIN + xc];
    }
    __syncthreads();
    const size_t pbase = ((size_t)(b * HIN + y)) * WIN;
    for (int j = tid; j < 64 * 128; j += 256) {
        int xc = j >> 6;
        int ci = j & 63;
        float v = xs[ci][xc];
        __nv_bfloat16 hi = __float2bfloat16(v);
        float r = v - __bfloat162float(hi);
        size_t o = (pbase + xc) * CIN + ci;
        g_xt_hi[o] = hi;
        g_xt_lo[o] = __float2bfloat16(r);
    }
}

__global__ __launch_bounds__(256)
void zero_pad_kernel()
{
    int idx = blockIdx.x * 256 + threadIdx.x;
    if (idx < XT_PAD * CIN) {
        size_t o = (size_t)XT_ROWS * CIN + idx;
        __nv_bfloat16 z = __float2bfloat16(0.f);
        g_xt_hi[o] = z;
        g_xt_lo[o] = z;
    }
}

// ---------------- Main mma.sync conv kernel ---------------------------------
// Grid (126 y, 2 x-halves, 32 b), 256 threads = 8 warps (4 m x 2 n).
// CTA tile: 128 co x 64 px. Warp tile: 32 co x 32 px.
// 95.6 KB smem -> 2 CTAs/SM (16 warps). W single-buffered per tap; the
// per-tap load bubble is hidden by the co-resident CTA's MMAs.
__global__ __launch_bounds__(256, 2)
void conv_mma_kernel(const float* __restrict__ bias)
{
    extern __shared__ __align__(128) char smem[];
    const uint32_t sb = smem_u32(smem);
    const int tid  = threadIdx.x;
    const int wid  = tid >> 5;
    const int lane = tid & 31;
    const int y  = blockIdx.x;
    const int xh = blockIdx.y;          // 0 / 1 : pixel half
    const int b  = blockIdx.z;
    const int x0 = xh * 64;
    const int wm = wid & 3;             // co block of 32
    const int wn = wid >> 2;            // px block of 32

    // ---- prologue: X union (both splits, 3 rows x 68 entries) ----
    const int rowstart = (b * HIN + y) * WIN + x0;
    for (int i = tid; i < 3264; i += 256) {            // 2*3*68*8
        int s = i / 1632;
        int r = i - s * 1632;
        int entry = r >> 3;                            // 0..203
        int h     = r & 7;
        int yrow  = entry / XENT;
        int px    = entry - yrow * XENT;
        size_t p  = (size_t)(rowstart + yrow * WIN + px);
        const char* srcb = s ? (const char*)g_xt_lo : (const char*)g_xt_hi;
        cp_async16(sb + s * XS_SPLIT + entry * XPITCH + h * 16,
                   srcb + p * 128 + h * 16);
    }
    CP_COMMIT();

    float acc[2][4][4];
#pragma unroll
    for (int i = 0; i < 2; i++)
#pragma unroll
        for (int j = 0; j < 4; j++)
#pragma unroll
            for (int k = 0; k < 4; k++) acc[i][j][k] = 0.f;

    for (int t = 0; t < 9; t++) {
        // ---- load W(t), single buffer ----
        if (t > 0) __syncthreads();                    // all warps done with W(t-1)
        for (int i = tid; i < 2048; i += 256) {        // 2 splits * 128co * 8
            int s  = i >> 10;
            int r  = i & 1023;
            int co = r >> 3;
            int h  = r & 7;
            const char* srcb = s ? (const char*)g_wa_lo : (const char*)g_wa_hi;
            cp_async16(sb + WS_OFF + s * WSPLIT + co * 144 + h * 16,
                       srcb + ((size_t)(t * 128 + co)) * 128 + h * 16);
        }
        CP_COMMIT();
        CP_WAIT0();                                    // also covers X on t=0
        __syncthreads();

        const int ky = t / 3;
        const int kx = t - 3 * ky;
        const uint32_t wsb = sb + WS_OFF;

#pragma unroll
        for (int kc = 0; kc < 4; kc++) {
            // ---- A fragments (hi+lo): 4 ldmatrix.x4 ----
            uint32_t ah[2][4], al[2][4];
#pragma unroll
            for (int mt = 0; mt < 2; mt++) {
                uint32_t rowco = (uint32_t)(wm * 32 + mt * 16 + (lane & 15));
                uint32_t aoff  = rowco * 144 + kc * 32 + ((lane >> 4) << 4);
                ldmx4(ah[mt][0], ah[mt][1], ah[mt][2], ah[mt][3], wsb + aoff);
                ldmx4(al[mt][0], al[mt][1], al[mt][2], al[mt][3], wsb + WSPLIT + aoff);
            }
            // ---- B fragments (hi+lo, 2 n-pairs): 4 ldmatrix.x4 ----
            uint32_t bh[2][4], bl[2][4];
#pragma unroll
            for (int pr = 0; pr < 2; pr++) {
                int pxl = wn * 32 + pr * 16 + (lane & 7) + ((lane >> 4) << 3) + kx;
                uint32_t entry = (uint32_t)(ky * XENT + pxl);
                uint32_t boff  = entry * XPITCH + kc * 32 + (((lane >> 3) & 1) << 4);
                ldmx4(bh[pr][0], bh[pr][1], bh[pr][2], bh[pr][3], sb + boff);
                ldmx4(bl[pr][0], bl[pr][1], bl[pr][2], bl[pr][3],
                      sb + XS_SPLIT + boff);
            }
            // ---- 24 MMAs, combo-major (reuse distance 8) ----
#pragma unroll
            for (int pr = 0; pr < 2; pr++)
#pragma unroll
                for (int mt = 0; mt < 2; mt++) {
                    mma16816(acc[mt][pr * 2 + 0], ah[mt], bh[pr][0], bh[pr][1]);
                    mma16816(acc[mt][pr * 2 + 1], ah[mt], bh[pr][2], bh[pr][3]);
                }
#pragma unroll
            for (int pr = 0; pr < 2; pr++)
#pragma unroll
                for (int mt = 0; mt < 2; mt++) {
                    mma16816(acc[mt][pr * 2 + 0], ah[mt], bl[pr][0], bl[pr][1]);
                    mma16816(acc[mt][pr * 2 + 1], ah[mt], bl[pr][2], bl[pr][3]);
                }
#pragma unroll
            for (int pr = 0; pr < 2; pr++)
#pragma unroll
                for (int mt = 0; mt < 2; mt++) {
                    mma16816(acc[mt][pr * 2 + 0], al[mt], bh[pr][0], bh[pr][1]);
                    mma16816(acc[mt][pr * 2 + 1], al[mt], bh[pr][2], bh[pr][3]);
                }
        }
    }
    __syncthreads();

    // ---- epilogue: accum -> smem [128][68] -> coalesced +bias STG ----
    float* smf = (float*)smem;
#pragma unroll
    for (int mt = 0; mt < 2; mt++)
#pragma unroll
        for (int nt = 0; nt < 4; nt++) {
            int co = wm * 32 + mt * 16 + (lane >> 2);
            int px = wn * 32 + (nt >> 1) * 16 + (nt & 1) * 8 + ((lane & 3) << 1);
            smf[co * XENT + px]           = acc[mt][nt][0];
            smf[co * XENT + px + 1]       = acc[mt][nt][1];
            smf[(co + 8) * XENT + px]     = acc[mt][nt][2];
            smf[(co + 8) * XENT + px + 1] = acc[mt][nt][3];
        }
    __syncthreads();

#pragma unroll 4
    for (int k = 0; k < 16; k++) {
        const int r = wid * 16 + k;
        const float bv = bias[r];
        float* dst = &g_y[(((size_t)b * COUT + r) * OH + y) * OW + x0];
        const float* srow = &smf[r * XENT];
#pragma unroll
        for (int j = 0; j < 2; j++) {
            const int xc = lane + 32 * j;
            if (x0 + xc < OW) dst[xc] = srow[xc] + bv;
        }
    }
}

// ---------------- GroupNorm stats -------------------------------------------
__global__ __launch_bounds__(256)
void gn_stats_kernel()
{
    const int bg = blockIdx.x;
    const int N  = CPG * OH * OW;                  // 127008
    const float4* __restrict__ p4 =
        reinterpret_cast<const float4*>(g_y + (size_t)bg * N);
    const int N4 = N / 4;

    const int tid = threadIdx.x;
    float s = 0.f, ss = 0.f;
    for (int i = tid; i < N4; i += 256) {
        float4 v = p4[i];
        s  += v.x + v.y + v.z + v.w;
        ss += v.x * v.x + v.y * v.y + v.z * v.z + v.w * v.w;
    }
    __shared__ float sh_s[256];
    __shared__ float sh_q[256];
    sh_s[tid] = s;
    sh_q[tid] = ss;
    __syncthreads();
    for (int off = 128; off > 0; off >>= 1) {
        if (tid < off) {
            sh_s[tid] += sh_s[tid + off];
            sh_q[tid] += sh_q[tid + off];
        }
        __syncthreads();
    }
    if (tid == 0) {
        float mean = sh_s[0] / (float)N;
        float var  = sh_q[0] / (float)N - mean * mean;
        g_mean[bg] = mean;
        g_rstd[bg] = rsqrtf(var + GN_EPS);
    }
}

// ---------------- Fused epilogue --------------------------------------------
__global__ __launch_bounds__(256)
void fuse_out_kernel(const float* __restrict__ gw,
                     const float* __restrict__ gb,
                     const float* __restrict__ sc,
                     float* __restrict__ out)
{
    const int total = BB * COUT * PH * PW;
    int idx = blockIdx.x * blockDim.x + threadIdx.x;
    if (idx >= total) return;

    int px = idx % PW;
    int t  = idx / PW;
    int py = t % PH;  t /= PH;
    int c  = t % COUT;
    int b  = t / COUT;

    const int bg     = b * NG + (c >> 3);
    const float mean = g_mean[bg];
    const float rstd = g_rstd[bg];
    const float gwc  = gw[c];
    const float scc  = sc[c];
    const float a    = rstd * gwc * scc;
    const float bb   = (gb[c] - mean * rstd * gwc) * scc;

    const float* yp = g_y + (((size_t)b * COUT + c) * OH + 2 * py) * OW + 2 * px;
    float v0 = fmaf(a, yp[0],      bb);
    float v1 = fmaf(a, yp[1],      bb);
    float v2 = fmaf(a, yp[OW],     bb);
    float v3 = fmaf(a, yp[OW + 1], bb);
    float m = fmaxf(fmaxf(v0, v1), fmaxf(v2, v3));
    out[idx] = fminf(fmaxf(m, 0.0f), 1.0f);
}

// ---------------------------------------------------------------------------
extern "C" void kernel_launch(void* const* d_in, const int* in_sizes, int n_in,
                              void* d_out, int out_size)
{
    const float* x      = (const float*)d_in[0];   // [32,64,128,128]
    const float* conv_w = (const float*)d_in[1];   // [128,64,3,3]
    const float* conv_b = (const float*)d_in[2];   // [128]
    const float* gn_w   = (const float*)d_in[3];   // [128]
    const float* gn_b   = (const float*)d_in[4];   // [128]
    const float* scale  = (const float*)d_in[5];   // [128,1,1]
    float* out = (float*)d_out;                    // [32,128,63,63]

    cudaFuncSetAttribute(conv_mma_kernel,
                         cudaFuncAttributeMaxDynamicSharedMemorySize, SMEM_TOTAL);

    prep_w_kernel<<<(9 * COUT * CIN + 255) / 256, 256>>>(conv_w);
    prep_x_kernel<<<dim3(HIN, BB), 256>>>(x);
    zero_pad_kernel<<<(XT_PAD * CIN + 255) / 256, 256>>>();

    conv_mma_kernel<<<dim3(OH, 2, BB), 256, SMEM_TOTAL>>>(conv_b);

    gn_stats_kernel<<<BB * NG, 256>>>();

    const int total = BB * COUT * PH * PW;
    fuse_out_kernel<<<(total + 255) / 256, 256>>>(gn_w, gn_b, scale, out);
}

// round 16
// speedup vs baseline: 4.2505x; 1.0530x over previous
#include <cuda_runtime.h>
#include <cuda_bf16.h>
#include <cstdint>

// Problem constants
#define BB    32
#define CIN   64
#define HIN   128
#define WIN   128
#define COUT  128
#define OH    126
#define OW    126
#define NG    16
#define CPG   8
#define PH    63
#define PW    63
#define GN_EPS 1e-5f

#define XT_ROWS (BB * HIN * WIN)     // 524288 flat pixel rows
#define XT_PAD  256
#define XT_TOT  (XT_ROWS + XT_PAD)

// Scratch
__device__ float g_y[(size_t)BB * COUT * OH * OW];
__device__ float g_mean[BB * NG];
__device__ float g_rstd[BB * NG];
__device__ float g_psum[512 * 128];   // per-(b,g) partial sums, 126 tiles used
__device__ float g_psq [512 * 128];
__device__ __nv_bfloat16 g_xt_hi[(size_t)XT_TOT * CIN];   // NHWC bf16 hi (128B/pixel)
__device__ __nv_bfloat16 g_xt_lo[(size_t)XT_TOT * CIN];   // NHWC bf16 lo
__device__ __nv_bfloat16 g_wa_hi[9 * COUT * CIN];         // per-tap W hi [tap][co][ci]
__device__ __nv_bfloat16 g_wa_lo[9 * COUT * CIN];

// ---------------- low-level helpers ----------------------------------------
__device__ __forceinline__ uint32_t smem_u32(const void* p) {
    uint32_t a;
    asm("{ .reg .u64 t; cvta.to.shared.u64 t, %1; cvt.u32.u64 %0, t; }"
        : "=r"(a) : "l"(p));
    return a;
}
__device__ __forceinline__ void cp_async16(uint32_t dst, const void* src) {
    asm volatile("cp.async.cg.shared.global [%0], [%1], 16;"
                 :: "r"(dst), "l"(src) : "memory");
}
#define CP_COMMIT() asm volatile("cp.async.commit_group;" ::: "memory")
#define CP_WAIT0()  asm volatile("cp.async.wait_group 0;" ::: "memory")

__device__ __forceinline__ void ldmx4(uint32_t& r0, uint32_t& r1,
                                      uint32_t& r2, uint32_t& r3, uint32_t addr) {
    asm volatile("ldmatrix.sync.aligned.m8n8.x4.shared.b16 {%0,%1,%2,%3}, [%4];"
                 : "=r"(r0), "=r"(r1), "=r"(r2), "=r"(r3) : "r"(addr));
}
__device__ __forceinline__ void mma16816(float* c, const uint32_t* a,
                                         uint32_t b0, uint32_t b1) {
    asm volatile(
        "mma.sync.aligned.m16n8k16.row.col.f32.bf16.bf16.f32 "
        "{%0,%1,%2,%3}, {%4,%5,%6,%7}, {%8,%9}, {%0,%1,%2,%3};"
        : "+f"(c[0]), "+f"(c[1]), "+f"(c[2]), "+f"(c[3])
        : "r"(a[0]), "r"(a[1]), "r"(a[2]), "r"(a[3]), "r"(b0), "r"(b1));
}

// ---------------- smem layout (64co x 64px x 2row CTA) ----------------------
#define XPITCH   144                      // bytes per pixel entry (128 + pad)
#define XENT     68                       // entries per y-row
#define XROWS    4                        // input rows resident (2 out rows + 2)
#define XS_SPLIT (XROWS * XENT * XPITCH)  // 39168 per split
#define WS_OFF   (2 * XS_SPLIT)           // 78336
#define WSPLIT   (64 * 144)               // 9216 per split
#define SMEM_TOTAL (WS_OFF + 2 * WSPLIT)  // 96768 -> 2 CTAs / SM

// ---------------- Prepass kernels -------------------------------------------
__global__ __launch_bounds__(256)
void prep_w_kernel(const float* __restrict__ w)
{
    int idx = blockIdx.x * 256 + threadIdx.x;          // (tap*128 + co)*64 + ci
    if (idx >= 9 * COUT * CIN) return;
    int ci  = idx & 63;
    int t2  = idx >> 6;
    int co  = t2 & 127;
    int tap = t2 >> 7;
    float v = w[((size_t)co * CIN + ci) * 9 + tap];
    __nv_bfloat16 hi = __float2bfloat16(v);
    float r = v - __bfloat162float(hi);
    g_wa_hi[idx] = hi;
    g_wa_lo[idx] = __float2bfloat16(r);
}

__global__ __launch_bounds__(256)
void prep_x_kernel(const float* __restrict__ x)
{
    __shared__ float xs[64][129];
    const int y = blockIdx.x;
    const int b = blockIdx.y;
    const int tid = threadIdx.x;
    for (int i = tid; i < 64 * 128; i += 256) {
        int ci = i >> 7;
        int xc = i & 127;
        xs[ci][xc] = x[(((size_t)b * CIN + ci) * HIN + y) * WIN + xc];
    }
    __syncthreads();
    const size_t pbase = ((size_t)(b * HIN + y)) * WIN;
    for (int j = tid; j < 64 * 128; j += 256) {
        int xc = j >> 6;
        int ci = j & 63;
        float v = xs[ci][xc];
        __nv_bfloat16 hi = __float2bfloat16(v);
        float r = v - __bfloat162float(hi);
        size_t o = (pbase + xc) * CIN + ci;
        g_xt_hi[o] = hi;
        g_xt_lo[o] = __float2bfloat16(r);
    }
}

__global__ __launch_bounds__(256)
void zero_pad_kernel()
{
    int idx = blockIdx.x * 256 + threadIdx.x;
    if (idx < XT_PAD * CIN) {
        size_t o = (size_t)XT_ROWS * CIN + idx;
        __nv_bfloat16 z = __float2bfloat16(0.f);
        g_xt_hi[o] = z;
        g_xt_lo[o] = z;
    }
}

// ---------------- Main mma.sync conv kernel ---------------------------------
// Grid (63 ypairs, 2 xh, 64 = b*2+cohalf). 256 threads = 8 warps
// (wm: 2 co-blocks of 32, wn: 2 px-blocks of 32, wr: 2 output rows).
// CTA tile: 64 co x 64 px x 2 rows. W slice (64 co) reused across both rows
// -> halved W L2 traffic vs 128co x 1row. GN partial stats fused in epilogue.
__global__ __launch_bounds__(256, 2)
void conv_mma_kernel(const float* __restrict__ bias)
{
    extern __shared__ __align__(128) char smem[];
    const uint32_t sb = smem_u32(smem);
    const int tid  = threadIdx.x;
    const int wid  = tid >> 5;
    const int lane = tid & 31;
    const int ypair = blockIdx.x;       // 0..62
    const int xh    = blockIdx.y;       // 0 / 1
    const int bz    = blockIdx.z;       // b*2 + ch
    const int b  = bz >> 1;
    const int ch = bz & 1;
    const int co0 = ch * 64;
    const int y0  = ypair * 2;
    const int x0  = xh * 64;
    const int wm = wid & 1;             // co block of 32
    const int wn = (wid >> 1) & 1;      // px block of 32
    const int wr = wid >> 2;            // output row 0/1

    // ---- prologue: X (both splits, 4 rows x 68 entries) ----
    const int rowstart = (b * HIN + y0) * WIN + x0;
    for (int i = tid; i < 4352; i += 256) {            // 2*4*68*8
        int s = i / 2176;
        int r = i - s * 2176;
        int entry = r >> 3;                            // 0..271
        int h     = r & 7;
        int yrow  = entry / XENT;
        int px    = entry - yrow * XENT;
        size_t p  = (size_t)(rowstart + yrow * WIN + px);
        const char* srcb = s ? (const char*)g_xt_lo : (const char*)g_xt_hi;
        cp_async16(sb + s * XS_SPLIT + entry * XPITCH + h * 16,
                   srcb + p * 128 + h * 16);
    }
    CP_COMMIT();

    float acc[2][4][4];
#pragma unroll
    for (int i = 0; i < 2; i++)
#pragma unroll
        for (int j = 0; j < 4; j++)
#pragma unroll
            for (int k = 0; k < 4; k++) acc[i][j][k] = 0.f;

    for (int t = 0; t < 9; t++) {
        if (t > 0) __syncthreads();                    // all warps done with W(t-1)
        // ---- load W(t): 64 co slice, hi+lo ----
        for (int i = tid; i < 1024; i += 256) {        // 2 splits * 64co * 8
            int s  = i >> 9;
            int r  = i & 511;
            int co = r >> 3;
            int h  = r & 7;
            const char* srcb = s ? (const char*)g_wa_lo : (const char*)g_wa_hi;
            cp_async16(sb + WS_OFF + s * WSPLIT + co * 144 + h * 16,
                       srcb + ((size_t)(t * 128 + co0 + co)) * 128 + h * 16);
        }
        CP_COMMIT();
        CP_WAIT0();                                    // also covers X on t=0
        __syncthreads();

        const int ky = t / 3;
        const int kx = t - 3 * ky;
        const uint32_t wsb = sb + WS_OFF;
        const int xr = wr + ky;                        // X row for this warp

#pragma unroll
        for (int kc = 0; kc < 4; kc++) {
            uint32_t ah[2][4], al[2][4];
#pragma unroll
            for (int mt = 0; mt < 2; mt++) {
                uint32_t rowco = (uint32_t)(wm * 32 + mt * 16 + (lane & 15));
                uint32_t aoff  = rowco * 144 + kc * 32 + ((lane >> 4) << 4);
                ldmx4(ah[mt][0], ah[mt][1], ah[mt][2], ah[mt][3], wsb + aoff);
                ldmx4(al[mt][0], al[mt][1], al[mt][2], al[mt][3], wsb + WSPLIT + aoff);
            }
            uint32_t bh[2][4], bl[2][4];
#pragma unroll
            for (int pr = 0; pr < 2; pr++) {
                int pxl = wn * 32 + pr * 16 + (lane & 7) + ((lane >> 4) << 3) + kx;
                uint32_t entry = (uint32_t)(xr * XENT + pxl);
                uint32_t boff  = entry * XPITCH + kc * 32 + (((lane >> 3) & 1) << 4);
                ldmx4(bh[pr][0], bh[pr][1], bh[pr][2], bh[pr][3], sb + boff);
                ldmx4(bl[pr][0], bl[pr][1], bl[pr][2], bl[pr][3],
                      sb + XS_SPLIT + boff);
            }
#pragma unroll
            for (int pr = 0; pr < 2; pr++)
#pragma unroll
                for (int mt = 0; mt < 2; mt++) {
                    mma16816(acc[mt][pr * 2 + 0], ah[mt], bh[pr][0], bh[pr][1]);
                    mma16816(acc[mt][pr * 2 + 1], ah[mt], bh[pr][2], bh[pr][3]);
                }
#pragma unroll
            for (int pr = 0; pr < 2; pr++)
#pragma unroll
                for (int mt = 0; mt < 2; mt++) {
                    mma16816(acc[mt][pr * 2 + 0], ah[mt], bl[pr][0], bl[pr][1]);
                    mma16816(acc[mt][pr * 2 + 1], ah[mt], bl[pr][2], bl[pr][3]);
                }
#pragma unroll
            for (int pr = 0; pr < 2; pr++)
#pragma unroll
                for (int mt = 0; mt < 2; mt++) {
                    mma16816(acc[mt][pr * 2 + 0], al[mt], bh[pr][0], bh[pr][1]);
                    mma16816(acc[mt][pr * 2 + 1], al[mt], bh[pr][2], bh[pr][3]);
                }
        }
    }

    // ---- epilogue: per row: accum -> smf -> +bias STG + GN partial stats ----
    float* smf = (float*)smem;                 // [64co][68] fp32 (reuses X)
    float gsum = 0.f, gsq = 0.f;               // warp wid == group (within half)
#pragma unroll
    for (int row = 0; row < 2; row++) {
        __syncthreads();                       // smf region free
        if (wr == row) {
#pragma unroll
            for (int mt = 0; mt < 2; mt++)
#pragma unroll
                for (int nt = 0; nt < 4; nt++) {
                    int co = wm * 32 + mt * 16 + (lane >> 2);
                    int px = wn * 32 + (nt >> 1) * 16 + (nt & 1) * 8 + ((lane & 3) << 1);
                    smf[co * XENT + px]           = acc[mt][nt][0];
                    smf[co * XENT + px + 1]       = acc[mt][nt][1];
                    smf[(co + 8) * XENT + px]     = acc[mt][nt][2];
                    smf[(co + 8) * XENT + px + 1] = acc[mt][nt][3];
                }
        }
        __syncthreads();
        const int oy = y0 + row;
#pragma unroll
        for (int k = 0; k < 8; k++) {
            const int r = wid * 8 + k;
            const float bv = bias[co0 + r];
            float* dst = &g_y[(((size_t)b * COUT + co0 + r) * OH + oy) * OW + x0];
            const float* srow = &smf[r * XENT];
#pragma unroll
            for (int j = 0; j < 2; j++) {
                const int xc = lane + 32 * j;
                if (x0 + xc < OW) {
                    float v = srow[xc] + bv;
                    dst[xc] = v;
                    gsum += v;
                    gsq  += v * v;
                }
            }
        }
    }
    // warp-level reduce: warp wid covers exactly group (ch*8 + wid)
#pragma unroll
    for (int off = 16; off > 0; off >>= 1) {
        gsum += __shfl_xor_sync(0xffffffffu, gsum, off);
        gsq  += __shfl_xor_sync(0xffffffffu, gsq,  off);
    }
    if (lane == 0) {
        const int bg   = b * NG + ch * 8 + wid;
        const int tile = ypair * 2 + xh;       // 0..125
        g_psum[bg * 128 + tile] = gsum;
        g_psq [bg * 128 + tile] = gsq;
    }
}

// ---------------- GN stats finish (tiny) -------------------------------------
__global__ __launch_bounds__(256)
void gn_finish_kernel()
{
    const int bg = blockIdx.x * 256 + threadIdx.x;
    if (bg >= BB * NG) return;
    const int N = CPG * OH * OW;               // 127008
    float s = 0.f, q = 0.f;
    for (int t = 0; t < 126; t++) {
        s += g_psum[bg * 128 + t];
        q += g_psq [bg * 128 + t];
    }
    float mean = s / (float)N;
    float var  = q / (float)N - mean * mean;
    g_mean[bg] = mean;
    g_rstd[bg] = rsqrtf(var + GN_EPS);
}

// ---------------- Fused epilogue --------------------------------------------
__global__ __launch_bounds__(256)
void fuse_out_kernel(const float* __restrict__ gw,
                     const float* __restrict__ gb,
                     const float* __restrict__ sc,
                     float* __restrict__ out)
{
    const int total = BB * COUT * PH * PW;
    int idx = blockIdx.x * blockDim.x + threadIdx.x;
    if (idx >= total) return;

    int px = idx % PW;
    int t  = idx / PW;
    int py = t % PH;  t /= PH;
    int c  = t % COUT;
    int b  = t / COUT;

    const int bg     = b * NG + (c >> 3);
    const float mean = g_mean[bg];
    const float rstd = g_rstd[bg];
    const float gwc  = gw[c];
    const float scc  = sc[c];
    const float a    = rstd * gwc * scc;
    const float bb   = (gb[c] - mean * rstd * gwc) * scc;

    const float* yp = g_y + (((size_t)b * COUT + c) * OH + 2 * py) * OW + 2 * px;
    float v0 = fmaf(a, yp[0],      bb);
    float v1 = fmaf(a, yp[1],      bb);
    float v2 = fmaf(a, yp[OW],     bb);
    float v3 = fmaf(a, yp[OW + 1], bb);
    float m = fmaxf(fmaxf(v0, v1), fmaxf(v2, v3));
    out[idx] = fminf(fmaxf(m, 0.0f), 1.0f);
}

// ---------------------------------------------------------------------------
extern "C" void kernel_launch(void* const* d_in, const int* in_sizes, int n_in,
                              void* d_out, int out_size)
{
    const float* x      = (const float*)d_in[0];   // [32,64,128,128]
    const float* conv_w = (const float*)d_in[1];   // [128,64,3,3]
    const float* conv_b = (const float*)d_in[2];   // [128]
    const float* gn_w   = (const float*)d_in[3];   // [128]
    const float* gn_b   = (const float*)d_in[4];   // [128]
    const float* scale  = (const float*)d_in[5];   // [128,1,1]
    float* out = (float*)d_out;                    // [32,128,63,63]

    cudaFuncSetAttribute(conv_mma_kernel,
                         cudaFuncAttributeMaxDynamicSharedMemorySize, SMEM_TOTAL);

    prep_w_kernel<<<(9 * COUT * CIN + 255) / 256, 256>>>(conv_w);
    prep_x_kernel<<<dim3(HIN, BB), 256>>>(x);
    zero_pad_kernel<<<(XT_PAD * CIN + 255) / 256, 256>>>();

    conv_mma_kernel<<<dim3(63, 2, BB * 2), 256, SMEM_TOTAL>>>(conv_b);

    gn_finish_kernel<<<2, 256>>>();

    const int total = BB * COUT * PH * PW;
    fuse_out_kernel<<<(total + 255) / 256, 256>>>(gn_w, gn_b, scale, out);
}